// round 1
// baseline (speedup 1.0000x reference)
#include <cuda_runtime.h>
#include <cuda_bf16.h>

#define VOCAB  32000
#define NLABEL 16
#define NSTATE 64
#define BATCH  512
#define MAXLEN 512

// Precomputed by prep kernels (device globals: no allocation allowed).
__device__ float g_TexpT[NSTATE * NSTATE];   // [j*64 + i] = softmax(transition[i,:])[j]
__device__ float g_Oexp [NLABEL * NSTATE];   // [l*64 + s] = softmax(output[l,:])[s]
__device__ float g_lse  [VOCAB];             // logsumexp(emb[v,:])

// ---------------------------------------------------------------------------
// Prep 1: row softmax of transition (64 rows) and output (16 rows).
// grid = 80 blocks x 64 threads; block r handles one row.
// ---------------------------------------------------------------------------
__global__ void prep_softmax_kernel(const float* __restrict__ transition,
                                    const float* __restrict__ output) {
    const int r = blockIdx.x;    // 0..79
    const int i = threadIdx.x;   // 0..63
    const float* src = (r < NSTATE) ? (transition + r * NSTATE)
                                    : (output + (r - NSTATE) * NSTATE);
    float v = src[i];

    __shared__ float shm[2];
    __shared__ float shs[2];

    float m = v;
    #pragma unroll
    for (int d = 16; d; d >>= 1) m = fmaxf(m, __shfl_xor_sync(0xffffffffu, m, d));
    if ((i & 31) == 0) shm[i >> 5] = m;
    __syncthreads();
    m = fmaxf(shm[0], shm[1]);

    float e = expf(v - m);
    float s = e;
    #pragma unroll
    for (int d = 16; d; d >>= 1) s += __shfl_xor_sync(0xffffffffu, s, d);
    if ((i & 31) == 0) shs[i >> 5] = s;
    __syncthreads();
    s = shs[0] + shs[1];

    float val = e / s;
    if (r < NSTATE) g_TexpT[i * NSTATE + r] = val;          // transposed store
    else            g_Oexp[(r - NSTATE) * NSTATE + i] = val;
}

// ---------------------------------------------------------------------------
// Prep 2: per-vocab-row logsumexp of emb. One warp per row, 2 elems/lane.
// ---------------------------------------------------------------------------
__global__ void prep_lse_kernel(const float* __restrict__ emb) {
    const int gw   = (blockIdx.x * blockDim.x + threadIdx.x) >> 5;  // row id
    const int lane = threadIdx.x & 31;
    if (gw >= VOCAB) return;
    const float* row = emb + gw * NSTATE;
    // raw in (-0.5, 0.5): no overflow concerns, skip max-subtraction.
    float s = expf(row[lane]) + expf(row[lane + 32]);
    #pragma unroll
    for (int d = 16; d; d >>= 1) s += __shfl_xor_sync(0xffffffffu, s, d);
    if (lane == 0) g_lse[gw] = logf(s);
}

// ---------------------------------------------------------------------------
// Main: one block per batch element, 64 threads (thread i owns state i).
// Scaled real-space forward recurrence:
//   G_0[i]   = exp(raw_0[i])
//   lm_t     = log(G_t[0])                       (uniform rescale, cancels exactly)
//   G_{t}[i] = exp(raw_t[i] - lm_{t-1}) * sum_j Texp[i][j] * G_{t-1}[j]
//   hidden[i] = log(G_{L-1}[i]) + sum_{t<L-1} lm_t - sum_{t<L} lse_vocab[tok_t]
//   score[l]  = log( sum_s Oexp[l][s] * G_{L-1}[s] ) + off - S
// No cross-thread reductions in the step loop; one __syncthreads per step.
// ---------------------------------------------------------------------------
__global__ void __launch_bounds__(NSTATE) hmm_forward_kernel(
    const int*   __restrict__ sentences,
    const int*   __restrict__ length,
    const float* __restrict__ emb,
    float*       __restrict__ out)
{
    const int b   = blockIdx.x;
    const int tid = threadIdx.x;

    __shared__ __align__(16) float G[2][NSTATE];

    const int  L    = length[b];
    const int* sent = sentences + b * MAXLEN;

    // Transition row for state `tid`, kept in registers (coalesced load from
    // the transposed table).
    float T[NSTATE];
    #pragma unroll
    for (int j = 0; j < NSTATE; ++j) T[j] = __ldg(&g_TexpT[j * NSTATE + tid]);

    // ---- t = 0 ----
    const int tok0 = __ldg(&sent[0]);
    float raw0 = __ldg(&emb[tok0 * NSTATE + tid]);
    float S    = __ldg(&g_lse[tok0]);            // accumulated emission normalizers
    G[0][tid]  = __expf(raw0);

    // Prefetch pipeline for t+1 / t+2.
    float raw_n = 0.f, lse_n = 0.f;
    if (L > 1) {
        const int t1 = __ldg(&sent[1]);
        raw_n = __ldg(&emb[t1 * NSTATE + tid]);
        lse_n = __ldg(&g_lse[t1]);
    }
    int tok_nn = (L > 2) ? __ldg(&sent[2]) : 0;
    __syncthreads();

    float off = 0.f;
    int   buf = 0;

    for (int t = 1; t < L; ++t) {
        // Uniform rescale constant from previous step's state 0 (broadcast LDS).
        const float lm = __logf(G[buf][0]);
        off += lm;

        const float rw = raw_n;
        S += lse_n;

        // Prefetch step t+1 emission row + token t+2.
        if (t + 1 < L) {
            raw_n = __ldg(&emb[tok_nn * NSTATE + tid]);
            lse_n = __ldg(&g_lse[tok_nn]);
        }
        if (t + 2 < L) tok_nn = __ldg(&sent[t + 2]);

        const float p = __expf(rw - lm);

        // 64-wide fp32 matvec from shared (vectorized broadcast loads).
        const float4* Gv = reinterpret_cast<const float4*>(G[buf]);
        float s0 = 0.f, s1 = 0.f, s2 = 0.f, s3 = 0.f;
        #pragma unroll
        for (int jv = 0; jv < NSTATE / 4; ++jv) {
            const float4 g = Gv[jv];
            s0 = fmaf(T[4 * jv + 0], g.x, s0);
            s1 = fmaf(T[4 * jv + 1], g.y, s1);
            s2 = fmaf(T[4 * jv + 2], g.z, s2);
            s3 = fmaf(T[4 * jv + 3], g.w, s3);
        }
        const float s  = (s0 + s1) + (s2 + s3);
        const float Gn = s * p;

        buf ^= 1;
        G[buf][tid] = Gn;
        __syncthreads();
    }

    // ---- readout: threads 0..15 each compute one label ----
    if (tid < NLABEL) {
        const float* O = g_Oexp + tid * NSTATE;
        const float* Gf = G[buf];
        float a0 = 0.f, a1 = 0.f, a2 = 0.f, a3 = 0.f;
        #pragma unroll
        for (int j4 = 0; j4 < NSTATE / 4; ++j4) {
            a0 = fmaf(__ldg(&O[4 * j4 + 0]), Gf[4 * j4 + 0], a0);
            a1 = fmaf(__ldg(&O[4 * j4 + 1]), Gf[4 * j4 + 1], a1);
            a2 = fmaf(__ldg(&O[4 * j4 + 2]), Gf[4 * j4 + 2], a2);
            a3 = fmaf(__ldg(&O[4 * j4 + 3]), Gf[4 * j4 + 3], a3);
        }
        out[b * NLABEL + tid] = __logf((a0 + a1) + (a2 + a3)) + off - S;
    }
}

// ---------------------------------------------------------------------------
extern "C" void kernel_launch(void* const* d_in, const int* in_sizes, int n_in,
                              void* d_out, int out_size) {
    const int*   sentences  = nullptr;
    const int*   length     = nullptr;
    const float* emb        = nullptr;
    const float* transition = nullptr;
    const float* output     = nullptr;

    // Robust mapping by element count (all five are distinct).
    for (int i = 0; i < n_in; ++i) {
        switch (in_sizes[i]) {
            case BATCH * MAXLEN:   sentences  = (const int*)  d_in[i]; break;
            case BATCH:            length     = (const int*)  d_in[i]; break;
            case VOCAB * NSTATE:   emb        = (const float*)d_in[i]; break;
            case NSTATE * NSTATE:  transition = (const float*)d_in[i]; break;
            case NLABEL * NSTATE:  output     = (const float*)d_in[i]; break;
            default: break;
        }
    }

    prep_softmax_kernel<<<NSTATE + NLABEL, NSTATE>>>(transition, output);
    prep_lse_kernel<<<(VOCAB * 32 + 127) / 128, 128>>>(emb);
    hmm_forward_kernel<<<BATCH, NSTATE>>>(sentences, length, emb, (float*)d_out);
}

// round 2
// speedup vs baseline: 1.5556x; 1.5556x over previous
#include <cuda_runtime.h>
#include <cuda_bf16.h>

#define VOCAB  32000
#define NLABEL 16
#define NSTATE 64
#define BATCH  512
#define MAXLEN 512

typedef unsigned long long ull;

// Packed f32x2 ops (sm_103a; SASS FFMA2 — PTX-only path).
#define FMA2(d, a, b, c) \
    asm("fma.rn.f32x2 %0, %1, %2, %3;" : "=l"(d) : "l"(a), "l"(b), "l"(c))
#define ADD2(d, a, b) \
    asm("add.rn.f32x2 %0, %1, %2;" : "=l"(d) : "l"(a), "l"(b))

// Precomputed tables (device globals: no allocation allowed).
// g_Tpack layout: float pair (Texp[r][2jv], Texp[r][2jv+1]) at
// g_Tpack[jv*128 + r*2 + {0,1}] -> one 8B load per pair, coalesced over r.
__device__ __align__(16) float g_Tpack[NSTATE * NSTATE];
__device__ float g_Oexp[NLABEL * NSTATE];   // [l*64 + s] = softmax(output[l,:])[s]
__device__ float g_lse [VOCAB];             // logsumexp(emb[v,:])

// ---------------------------------------------------------------------------
// Prep 1: row softmax of transition (64 rows) and output (16 rows).
// ---------------------------------------------------------------------------
__global__ void prep_softmax_kernel(const float* __restrict__ transition,
                                    const float* __restrict__ output) {
    const int r = blockIdx.x;    // 0..79
    const int i = threadIdx.x;   // 0..63
    const float* src = (r < NSTATE) ? (transition + r * NSTATE)
                                    : (output + (r - NSTATE) * NSTATE);
    float v = src[i];

    __shared__ float shm[2];
    __shared__ float shs[2];

    float m = v;
    #pragma unroll
    for (int d = 16; d; d >>= 1) m = fmaxf(m, __shfl_xor_sync(0xffffffffu, m, d));
    if ((i & 31) == 0) shm[i >> 5] = m;
    __syncthreads();
    m = fmaxf(shm[0], shm[1]);

    float e = expf(v - m);
    float s = e;
    #pragma unroll
    for (int d = 16; d; d >>= 1) s += __shfl_xor_sync(0xffffffffu, s, d);
    if ((i & 31) == 0) shs[i >> 5] = s;
    __syncthreads();
    s = shs[0] + shs[1];

    float val = e / s;
    if (r < NSTATE) g_Tpack[(i >> 1) * 128 + r * 2 + (i & 1)] = val;
    else            g_Oexp[(r - NSTATE) * NSTATE + i] = val;
}

// ---------------------------------------------------------------------------
// Prep 2: per-vocab-row logsumexp of emb. One warp per row, 2 elems/lane.
// ---------------------------------------------------------------------------
__global__ void prep_lse_kernel(const float* __restrict__ emb) {
    const int gw   = (blockIdx.x * blockDim.x + threadIdx.x) >> 5;
    const int lane = threadIdx.x & 31;
    if (gw >= VOCAB) return;
    const float* row = emb + gw * NSTATE;
    float s = expf(row[lane]) + expf(row[lane + 32]);
    #pragma unroll
    for (int d = 16; d; d >>= 1) s += __shfl_xor_sync(0xffffffffu, s, d);
    if (lane == 0) g_lse[gw] = logf(s);
}

// ---------------------------------------------------------------------------
// Main: one block per batch element, 64 threads (thread i owns state i).
// Unnormalized real-space recurrence with periodic renormalization:
//   G_0[i]  = exp(raw_0[i])
//   G_t[i]  = exp(raw_t[i]) * sum_j Texp[i][j] * G_{t-1}[j]
//   every 16 steps: scale by rcp(G[0]); off += log(G[0])
//   hidden correction: S = sum_{t<L} lse_vocab[tok_t]
// Loop has NO cross-thread reductions, NO MUFU on common steps; emission rows
// are prefetched 3 steps deep (hides L2/DRAM gather latency); tokens staged in
// SMEM. FMA issue halved via packed f32x2 FMAs.
// ---------------------------------------------------------------------------
__global__ void __launch_bounds__(NSTATE) hmm_forward_kernel(
    const int*   __restrict__ sentences,
    const int*   __restrict__ length,
    const float* __restrict__ emb,
    float*       __restrict__ out)
{
    const int b   = blockIdx.x;
    const int tid = threadIdx.x;

    __shared__ __align__(16) float G[2][NSTATE];
    __shared__ int   toks[MAXLEN];
    __shared__ float red[2];

    const int  L    = length[b];
    const int  Lm1  = L - 1;
    const int* sent = sentences + b * MAXLEN;

    // Stage tokens in SMEM (coalesced).
    for (int i = tid; i < L; i += NSTATE) toks[i] = __ldg(&sent[i]);

    // Transition row for state `tid`, as 32 packed f32x2 register pairs.
    ull T2[NSTATE / 2];
    #pragma unroll
    for (int jv = 0; jv < NSTATE / 2; ++jv)
        T2[jv] = *reinterpret_cast<const ull*>(&g_Tpack[jv * 128 + tid * 2]);

    // ---- t = 0 ----
    const int tok0 = __ldg(&sent[0]);
    G[0][tid] = __expf(__ldg(&emb[tok0 * NSTATE + tid]));
    __syncthreads();   // G[0] + toks visible

    // 3-deep emission-row prefetch pipeline (clamped indices: loads always
    // valid; values past L-1 never used).
    float r1 = __ldg(&emb[toks[min(1, Lm1)] * NSTATE + tid]);
    float r2 = __ldg(&emb[toks[min(2, Lm1)] * NSTATE + tid]);
    float r3 = __ldg(&emb[toks[min(3, Lm1)] * NSTATE + tid]);

    float off = 0.f;
    int   buf = 0;

    for (int t = 1; t < L; ++t) {
        float e = __expf(r1);      // raw in (-0.5,0.5): exp in [0.6,1.65]
        r1 = r2; r2 = r3;
        r3 = __ldg(&emb[toks[min(t + 3, Lm1)] * NSTATE + tid]);

        if ((t & 15) == 0) {       // periodic renormalization (uniform branch)
            const float g0 = G[buf][0];
            float c;
            asm("rcp.approx.f32 %0, %1;" : "=f"(c) : "f"(g0));
            e *= c;
            off += __logf(g0);
        }

        // 64-wide fp32 matvec from shared, packed f32x2 (32 FFMA2).
        const ulonglong2* Gv = reinterpret_cast<const ulonglong2*>(G[buf]);
        ull a0 = 0ull, a1 = 0ull, a2 = 0ull, a3 = 0ull;
        #pragma unroll
        for (int jv = 0; jv < 16; jv += 2) {
            const ulonglong2 u = Gv[jv];
            const ulonglong2 v = Gv[jv + 1];
            FMA2(a0, T2[2 * jv + 0], u.x, a0);
            FMA2(a1, T2[2 * jv + 1], u.y, a1);
            FMA2(a2, T2[2 * jv + 2], v.x, a2);
            FMA2(a3, T2[2 * jv + 3], v.y, a3);
        }
        ull b0, b1, bb;
        ADD2(b0, a0, a2);
        ADD2(b1, a1, a3);
        ADD2(bb, b0, b1);
        float lo, hi;
        asm("mov.b64 {%0, %1}, %2;" : "=f"(lo), "=f"(hi) : "l"(bb));
        const float Gn = (lo + hi) * e;

        buf ^= 1;
        G[buf][tid] = Gn;
        __syncthreads();
    }

    // ---- emission-normalizer sum S = sum_{t<L} lse[tok_t] (off hot loop) ----
    float S = 0.f;
    for (int i = tid; i < L; i += NSTATE) S += __ldg(&g_lse[toks[i]]);
    #pragma unroll
    for (int d = 16; d; d >>= 1) S += __shfl_xor_sync(0xffffffffu, S, d);
    if ((tid & 31) == 0) red[tid >> 5] = S;
    __syncthreads();
    S = red[0] + red[1];

    // ---- readout: threads 0..15 each compute one label ----
    if (tid < NLABEL) {
        const float* O  = g_Oexp + tid * NSTATE;
        const float* Gf = G[buf];
        float a0 = 0.f, a1 = 0.f, a2 = 0.f, a3 = 0.f;
        #pragma unroll
        for (int j4 = 0; j4 < NSTATE / 4; ++j4) {
            a0 = fmaf(__ldg(&O[4 * j4 + 0]), Gf[4 * j4 + 0], a0);
            a1 = fmaf(__ldg(&O[4 * j4 + 1]), Gf[4 * j4 + 1], a1);
            a2 = fmaf(__ldg(&O[4 * j4 + 2]), Gf[4 * j4 + 2], a2);
            a3 = fmaf(__ldg(&O[4 * j4 + 3]), Gf[4 * j4 + 3], a3);
        }
        out[b * NLABEL + tid] = __logf((a0 + a1) + (a2 + a3)) + off - S;
    }
}

// ---------------------------------------------------------------------------
extern "C" void kernel_launch(void* const* d_in, const int* in_sizes, int n_in,
                              void* d_out, int out_size) {
    const int*   sentences  = nullptr;
    const int*   length     = nullptr;
    const float* emb        = nullptr;
    const float* transition = nullptr;
    const float* output     = nullptr;

    for (int i = 0; i < n_in; ++i) {
        switch (in_sizes[i]) {
            case BATCH * MAXLEN:   sentences  = (const int*)  d_in[i]; break;
            case BATCH:            length     = (const int*)  d_in[i]; break;
            case VOCAB * NSTATE:   emb        = (const float*)d_in[i]; break;
            case NSTATE * NSTATE:  transition = (const float*)d_in[i]; break;
            case NLABEL * NSTATE:  output     = (const float*)d_in[i]; break;
            default: break;
        }
    }

    prep_softmax_kernel<<<NSTATE + NLABEL, NSTATE>>>(transition, output);
    prep_lse_kernel<<<(VOCAB * 32 + 127) / 128, 128>>>(emb);
    hmm_forward_kernel<<<BATCH, NSTATE>>>(sentences, length, emb, (float*)d_out);
}

// round 3
// speedup vs baseline: 1.7215x; 1.1066x over previous
#include <cuda_runtime.h>
#include <cuda_bf16.h>

#define VOCAB  32000
#define NLABEL 16
#define NSTATE 64
#define BATCH  512
#define MAXLEN 512

typedef unsigned long long ull;

// Packed f32x2 ops (sm_103a; SASS FFMA2 — PTX-only path).
#define FMA2(d, a, b, c) \
    asm("fma.rn.f32x2 %0, %1, %2, %3;" : "=l"(d) : "l"(a), "l"(b), "l"(c))
#define ADD2(d, a, b) \
    asm("add.rn.f32x2 %0, %1, %2;" : "=l"(d) : "l"(a), "l"(b))

// Precomputed tables (device globals: no allocation allowed).
// g_Tpack float layout: Texp[r][i] stored at (i>>1)*128 + r*2 + (i&1).
// As 8-byte pairs: ull index jv*64 + r = (Texp[r][2jv], Texp[r][2jv+1]).
__device__ __align__(16) float g_Tpack[NSTATE * NSTATE];
__device__ float g_Oexp[NLABEL * NSTATE];   // [l*64 + s] = softmax(output[l,:])[s]
__device__ float g_lse [VOCAB];             // logsumexp(emb[v,:])

// ---------------------------------------------------------------------------
// Prep 1: row softmax of transition (64 rows) and output (16 rows).
// ---------------------------------------------------------------------------
__global__ void prep_softmax_kernel(const float* __restrict__ transition,
                                    const float* __restrict__ output) {
    const int r = blockIdx.x;    // 0..79
    const int i = threadIdx.x;   // 0..63
    const float* src = (r < NSTATE) ? (transition + r * NSTATE)
                                    : (output + (r - NSTATE) * NSTATE);
    float v = src[i];

    __shared__ float shm[2];
    __shared__ float shs[2];

    float m = v;
    #pragma unroll
    for (int d = 16; d; d >>= 1) m = fmaxf(m, __shfl_xor_sync(0xffffffffu, m, d));
    if ((i & 31) == 0) shm[i >> 5] = m;
    __syncthreads();
    m = fmaxf(shm[0], shm[1]);

    float e = expf(v - m);
    float s = e;
    #pragma unroll
    for (int d = 16; d; d >>= 1) s += __shfl_xor_sync(0xffffffffu, s, d);
    if ((i & 31) == 0) shs[i >> 5] = s;
    __syncthreads();
    s = shs[0] + shs[1];

    float val = e / s;
    if (r < NSTATE) g_Tpack[(i >> 1) * 128 + r * 2 + (i & 1)] = val;
    else            g_Oexp[(r - NSTATE) * NSTATE + i] = val;
}

// ---------------------------------------------------------------------------
// Prep 2: per-vocab-row logsumexp of emb. One warp per row, 2 elems/lane.
// ---------------------------------------------------------------------------
__global__ void prep_lse_kernel(const float* __restrict__ emb) {
    const int gw   = (blockIdx.x * blockDim.x + threadIdx.x) >> 5;
    const int lane = threadIdx.x & 31;
    if (gw >= VOCAB) return;
    const float* row = emb + gw * NSTATE;
    float s = expf(row[lane]) + expf(row[lane + 32]);
    #pragma unroll
    for (int d = 16; d; d >>= 1) s += __shfl_xor_sync(0xffffffffu, s, d);
    if (lane == 0) g_lse[gw] = logf(s);
}

// ---------------------------------------------------------------------------
// Main: ONE WARP per batch element. Lane l owns states 2l and 2l+1.
// Warp-synchronous (no __syncthreads): G exchanged through SMEM with
// __syncwarp only. Transition rows live in 64 packed f32x2 register pairs.
// Unnormalized real-space recurrence, renormalized every 16 steps.
// ---------------------------------------------------------------------------
__global__ void __launch_bounds__(32) hmm_forward_kernel(
    const int*   __restrict__ sentences,
    const int*   __restrict__ length,
    const float* __restrict__ emb,
    float*       __restrict__ out)
{
    const int b    = blockIdx.x;
    const int lane = threadIdx.x;

    __shared__ __align__(16) float G[2][NSTATE];
    __shared__ int toks[MAXLEN];

    const int  L    = length[b];
    const int  Lm1  = L - 1;
    const int* sent = sentences + b * MAXLEN;

    // Stage tokens in SMEM (coalesced, 16 iterations max).
    for (int i = lane; i < L; i += 32) toks[i] = __ldg(&sent[i]);

    // Transition rows for states s0=2*lane, s1=2*lane+1:
    // TA[jv] = (Texp[s0][2jv], Texp[s0][2jv+1]), TB likewise for s1.
    // One LDG.128 per jv (16B per lane, coalesced).
    ull TA[NSTATE / 2], TB[NSTATE / 2];
    {
        const ulonglong2* Tp = reinterpret_cast<const ulonglong2*>(g_Tpack);
        #pragma unroll
        for (int jv = 0; jv < NSTATE / 2; ++jv) {
            const ulonglong2 p = __ldg(&Tp[jv * 32 + lane]);   // ull idx jv*64+2l
            TA[jv] = p.x;
            TB[jv] = p.y;
        }
    }

    // ---- t = 0 ----
    const int tok0 = __ldg(&sent[0]);
    const float2 raw0 = *reinterpret_cast<const float2*>(&emb[tok0 * NSTATE + 2 * lane]);
    *reinterpret_cast<float2*>(&G[0][2 * lane]) =
        make_float2(__expf(raw0.x), __expf(raw0.y));
    __syncwarp();   // G[0] + toks visible warp-wide

    // 3-deep emission-row prefetch (clamped indices: always valid loads).
    float2 r1 = *reinterpret_cast<const float2*>(&emb[toks[min(1, Lm1)] * NSTATE + 2 * lane]);
    float2 r2 = *reinterpret_cast<const float2*>(&emb[toks[min(2, Lm1)] * NSTATE + 2 * lane]);
    float2 r3 = *reinterpret_cast<const float2*>(&emb[toks[min(3, Lm1)] * NSTATE + 2 * lane]);

    float off = 0.f;
    int   buf = 0;

    for (int t = 1; t < L; ++t) {
        float eA = __expf(r1.x);
        float eB = __expf(r1.y);
        r1 = r2; r2 = r3;
        r3 = *reinterpret_cast<const float2*>(&emb[toks[min(t + 3, Lm1)] * NSTATE + 2 * lane]);

        if ((t & 15) == 0) {       // periodic renormalization (uniform branch)
            const float g0 = G[buf][0];
            float c;
            asm("rcp.approx.f32 %0, %1;" : "=f"(c) : "f"(g0));
            eA *= c;
            eB *= c;
            off += __logf(g0);
        }

        // Two 64-wide matvecs (states s0, s1) from shared G, packed f32x2.
        const ulonglong2* Gv = reinterpret_cast<const ulonglong2*>(G[buf]);
        ull a0 = 0ull, a1 = 0ull, b0 = 0ull, b1 = 0ull;
        #pragma unroll
        for (int jv = 0; jv < 16; ++jv) {
            const ulonglong2 g = Gv[jv];
            FMA2(a0, TA[2 * jv + 0], g.x, a0);
            FMA2(a1, TA[2 * jv + 1], g.y, a1);
            FMA2(b0, TB[2 * jv + 0], g.x, b0);
            FMA2(b1, TB[2 * jv + 1], g.y, b1);
        }
        ull as, bs;
        ADD2(as, a0, a1);
        ADD2(bs, b0, b1);
        float alo, ahi, blo, bhi;
        asm("mov.b64 {%0, %1}, %2;" : "=f"(alo), "=f"(ahi) : "l"(as));
        asm("mov.b64 {%0, %1}, %2;" : "=f"(blo), "=f"(bhi) : "l"(bs));
        const float GnA = (alo + ahi) * eA;
        const float GnB = (blo + bhi) * eB;

        buf ^= 1;
        *reinterpret_cast<float2*>(&G[buf][2 * lane]) = make_float2(GnA, GnB);
        __syncwarp();
    }

    // ---- emission-normalizer sum S = sum_{t<L} lse[tok_t] ----
    float S = 0.f;
    for (int i = lane; i < L; i += 32) S += __ldg(&g_lse[toks[i]]);
    #pragma unroll
    for (int d = 16; d; d >>= 1) S += __shfl_xor_sync(0xffffffffu, S, d);

    // ---- readout: lanes 0..15 each compute one label ----
    if (lane < NLABEL) {
        const float* O  = g_Oexp + lane * NSTATE;
        const float* Gf = G[buf];
        float a0 = 0.f, a1 = 0.f, a2 = 0.f, a3 = 0.f;
        #pragma unroll
        for (int j4 = 0; j4 < NSTATE / 4; ++j4) {
            a0 = fmaf(__ldg(&O[4 * j4 + 0]), Gf[4 * j4 + 0], a0);
            a1 = fmaf(__ldg(&O[4 * j4 + 1]), Gf[4 * j4 + 1], a1);
            a2 = fmaf(__ldg(&O[4 * j4 + 2]), Gf[4 * j4 + 2], a2);
            a3 = fmaf(__ldg(&O[4 * j4 + 3]), Gf[4 * j4 + 3], a3);
        }
        out[b * NLABEL + lane] = __logf((a0 + a1) + (a2 + a3)) + off - S;
    }
}

// ---------------------------------------------------------------------------
extern "C" void kernel_launch(void* const* d_in, const int* in_sizes, int n_in,
                              void* d_out, int out_size) {
    const int*   sentences  = nullptr;
    const int*   length     = nullptr;
    const float* emb        = nullptr;
    const float* transition = nullptr;
    const float* output     = nullptr;

    for (int i = 0; i < n_in; ++i) {
        switch (in_sizes[i]) {
            case BATCH * MAXLEN:   sentences  = (const int*)  d_in[i]; break;
            case BATCH:            length     = (const int*)  d_in[i]; break;
            case VOCAB * NSTATE:   emb        = (const float*)d_in[i]; break;
            case NSTATE * NSTATE:  transition = (const float*)d_in[i]; break;
            case NLABEL * NSTATE:  output     = (const float*)d_in[i]; break;
            default: break;
        }
    }

    prep_softmax_kernel<<<NSTATE + NLABEL, NSTATE>>>(transition, output);
    prep_lse_kernel<<<(VOCAB * 32 + 127) / 128, 128>>>(emb);
    hmm_forward_kernel<<<BATCH, 32>>>(sentences, length, emb, (float*)d_out);
}